// round 2
// baseline (speedup 1.0000x reference)
#include <cuda_runtime.h>

#define BB 8
#define CEMB 256
#define HH 96
#define WWD 96
#define HWP (HH*WWD)      // 9216
#define PH 24
#define PWd 24
#define KP (PH*PWd)       // 576

// scratch (static device globals — no runtime allocation)
__device__ float g_fi[BB*CEMB*KP];      // pooled init_embed (b,c,k)
__device__ float g_si[BB*2*KP];         // pooled init_seg   (b,s,k)
__device__ float g_extra[BB*8*HWP];     // ch: gmap0,gmap1,iseg0,iseg1,lmap0,lmap1,pseg0,pseg1
__device__ float g_h[BB*128*HWP];       // conv1 output
__device__ float g_w1t[264*9*128];      // W1 transposed to [ic][tap][oc]

// ---------------------------------------------------------------- pooling
__global__ void __launch_bounds__(256) pool_kernel(const float* __restrict__ init_embed,
                                                   const float* __restrict__ init_seg){
  int idx = blockIdx.x*256 + threadIdx.x;
  const int nfi = BB*CEMB*KP;
  if (idx < nfi){
    int k = idx % KP; int c = (idx/KP) % CEMB; int b = idx/(KP*CEMB);
    int py = k/PWd, px = k%PWd;
    const float* s = init_embed + (((size_t)(b*CEMB+c))*HH + py*4)*WWD + px*4;
    float acc = 0.f;
    #pragma unroll
    for (int i=0;i<4;i++)
      #pragma unroll
      for (int j=0;j<4;j++) acc += s[i*WWD+j];
    g_fi[idx] = acc*(1.f/16.f);
  } else if (idx < nfi + BB*2*KP){
    int r = idx - nfi;
    int k = r%KP; int c=(r/KP)%2; int b=r/(KP*2);
    int py=k/PWd, px=k%PWd;
    const float* s = init_seg + (((size_t)(b*2+c))*HH + py*4)*WWD + px*4;
    float acc=0.f;
    #pragma unroll
    for (int i=0;i<4;i++)
      #pragma unroll
      for (int j=0;j<4;j++) acc += s[i*WWD+j];
    g_si[r] = acc*(1.f/16.f);
  }
}

// ------------------------------------------- pack segs into extras + W1 transpose
__global__ void __launch_bounds__(256) prep_kernel(const float* __restrict__ init_seg,
                                                   const float* __restrict__ prev_seg,
                                                   const float* __restrict__ W1){
  int idx = blockIdx.x*256 + threadIdx.x;
  if (idx < BB*2*HWP){
    int px = idx % HWP; int s=(idx/HWP)%2; int b=idx/(2*HWP);
    g_extra[((size_t)(b*8+2+s))*HWP + px] = init_seg[idx];
    g_extra[((size_t)(b*8+6+s))*HWP + px] = prev_seg[idx];
  }
  if (idx < 128*264*9){
    int t = idx%9; int ic=(idx/9)%264; int oc=idx/(264*9);
    g_w1t[((size_t)ic*9+t)*128 + oc] = W1[idx];
  }
}

// ---------------------------------------------------------------- gmap (GEMM + max epilogue)
// per block: 64 pixels x all 576 k, K=256. thread = 4k x 4px register tile.
__global__ void __launch_bounds__(256) gmap_kernel(const float* __restrict__ cur_embed){
  __shared__ float sfi[16][64];
  __shared__ float scur[16][64];
  __shared__ float red[16][2][64];
  const int b   = blockIdx.y;
  const int px0 = blockIdx.x*64;
  const int tid = threadIdx.x;
  const int tx  = tid & 15, ty = tid >> 4;
  float best0[4], best1[4];
  #pragma unroll
  for (int j=0;j<4;j++){ best0[j]=-1e30f; best1[j]=-1e30f; }
  const float* __restrict__ curb = cur_embed + (size_t)b*CEMB*HWP + px0;
  const float* __restrict__ fib  = g_fi + (size_t)b*CEMB*KP;
  const float* __restrict__ sib  = g_si + b*2*KP;

  for (int kt=0; kt<KP; kt+=64){
    float acc[4][4];
    #pragma unroll
    for (int i=0;i<4;i++)
      #pragma unroll
      for (int j=0;j<4;j++) acc[i][j]=0.f;

    for (int ct=0; ct<CEMB; ct+=16){
      __syncthreads();
      #pragma unroll
      for (int l=0;l<4;l++){
        int e = tid + l*256;
        int ci = e>>6, kk = e&63;
        sfi[ci][kk]  = fib[(size_t)(ct+ci)*KP + kt + kk];
        scur[ci][kk] = curb[(size_t)(ct+ci)*HWP + kk];
      }
      __syncthreads();
      #pragma unroll
      for (int ci=0;ci<16;ci++){
        const float4 f4 = *(const float4*)&sfi[ci][ty*4];
        const float4 c4 = *(const float4*)&scur[ci][tx*4];
        float fk[4] = {f4.x,f4.y,f4.z,f4.w};
        float cp[4] = {c4.x,c4.y,c4.z,c4.w};
        #pragma unroll
        for (int i=0;i<4;i++)
          #pragma unroll
          for (int j=0;j<4;j++) acc[i][j] += fk[i]*cp[j];
      }
    }
    // fold si weighting + running max over k
    #pragma unroll
    for (int i=0;i<4;i++){
      int k = kt + ty*4 + i;
      float s0 = sib[k], s1 = sib[KP + k];
      #pragma unroll
      for (int j=0;j<4;j++){
        best0[j] = fmaxf(best0[j], acc[i][j]*s0);
        best1[j] = fmaxf(best1[j], acc[i][j]*s1);
      }
    }
  }
  #pragma unroll
  for (int j=0;j<4;j++){ red[ty][0][tx*4+j]=best0[j]; red[ty][1][tx*4+j]=best1[j]; }
  __syncthreads();
  if (tid < 128){
    int s = tid>>6, pp = tid&63;
    float m = red[0][s][pp];
    #pragma unroll
    for (int t=1;t<16;t++) m = fmaxf(m, red[t][s][pp]);
    g_extra[((size_t)(b*8+s))*HWP + px0 + pp] = m;
  }
}

// ---------------------------------------------------------------- local correlation (lmap)
// block = one row, 32 pixels. corr computed UNMASKED (mask factored into epilogue).
__global__ void __launch_bounds__(256) corr_kernel(const float* __restrict__ cur_embed,
                                                   const float* __restrict__ prev_embed,
                                                   const float* __restrict__ prev_seg){
  __shared__ float scur[16][32];
  __shared__ float sprev[16][9][40];
  __shared__ float scorr[32][82];
  const int b = blockIdx.z, y = blockIdx.y, x0 = blockIdx.x*32;
  const int tid = threadIdx.x;
  for (int l=tid; l<32*82; l+=256) (&scorr[0][0])[l]=0.f;
  const int pg = tid&7, dxg = (tid>>3)%3, dy = tid/24;   // valid when tid<216

  for (int ct=0; ct<CEMB; ct+=16){
    __syncthreads();
    for (int l=tid; l<16*32; l+=256){
      int ci=l>>5, pp=l&31;
      scur[ci][pp] = cur_embed[(((size_t)(b*CEMB+ct+ci))*HH + y)*WWD + x0+pp];
    }
    for (int l=tid; l<16*9*40; l+=256){
      int ci=l/360, r=(l/40)%9, cc=l%40;
      int yy=y-4+r, xx=x0-4+cc;
      float v=0.f;
      if (yy>=0 && yy<HH && xx>=0 && xx<WWD)
        v = prev_embed[(((size_t)(b*CEMB+ct+ci))*HH+yy)*WWD+xx];
      sprev[ci][r][cc]=v;
    }
    __syncthreads();
    if (tid < 216){
      float a[3][4];
      #pragma unroll
      for (int d=0;d<3;d++)
        #pragma unroll
        for (int j=0;j<4;j++) a[d][j]=0.f;
      #pragma unroll
      for (int ci=0;ci<16;ci++){
        float cu[4], pv[6];
        #pragma unroll
        for (int j=0;j<4;j++) cu[j]=scur[ci][pg*4+j];
        #pragma unroll
        for (int t=0;t<6;t++) pv[t]=sprev[ci][dy][pg*4+dxg*3+t];
        #pragma unroll
        for (int d=0;d<3;d++)
          #pragma unroll
          for (int j=0;j<4;j++) a[d][j] += cu[j]*pv[d+j];
      }
      #pragma unroll
      for (int d=0;d<3;d++)
        #pragma unroll
        for (int j=0;j<4;j++)
          scorr[pg*4+j][dy*9+dxg*3+d] += a[d][j];
    }
  }
  __syncthreads();
  if (tid < 64){
    int s = tid>>5, px = tid&31;
    int xg = x0+px;
    const float* __restrict__ seg = prev_seg + ((size_t)(b*2+s))*HWP;
    float best = -1e30f;
    for (int d2=0; d2<9; d2++){
      int yy=y-4+d2;
      #pragma unroll
      for (int dx=0; dx<9; dx++){
        int xx=xg-4+dx;
        float sv = (yy>=0&&yy<HH&&xx>=0&&xx<WWD) ? seg[yy*WWD+xx] : 0.f;
        best = fmaxf(best, scorr[px][d2*9+dx]*(1.f/256.f)*sv);
      }
    }
    g_extra[((size_t)(b*8+4+s))*HWP + y*WWD + xg] = best;
  }
}

// ---------------------------------------------------------------- conv1 264->128 3x3 + relu
// block: 64 oc x (8x8 px) tile; thread = 4oc x 4px.
__global__ void __launch_bounds__(256) conv1_kernel(const float* __restrict__ cur_decode,
                                                    const float* __restrict__ b1){
  __shared__ float sin[8][10][13];
  __shared__ float sw[8][9][64];
  const int b   = blockIdx.z;
  const int oct = blockIdx.y;
  const int ty0 = (blockIdx.x/12)*8, tx0 = (blockIdx.x%12)*8;
  const int tid = threadIdx.x;
  const int tx  = tid&15, ty = tid>>4;
  const int py  = tx>>1, pxl = (tx&1)*4;
  float acc[4][4];
  #pragma unroll
  for (int i=0;i<4;i++)
    #pragma unroll
    for (int j=0;j<4;j++) acc[i][j]=0.f;

  for (int icc=0; icc<264; icc+=8){
    __syncthreads();
    for (int l=tid; l<800; l+=256){
      int ci=l/100, r=(l/10)%10, cc=l%10;
      int ic = icc+ci;
      int yy=ty0-1+r, xx=tx0-1+cc;
      float v=0.f;
      if (yy>=0&&yy<HH&&xx>=0&&xx<WWD){
        if (ic<256) v = cur_decode[(((size_t)(b*256+ic))*HH+yy)*WWD+xx];
        else        v = g_extra[((size_t)(b*8+(ic-256)))*HWP + yy*WWD+xx];
      }
      sin[ci][r][cc]=v;
    }
    for (int l=tid; l<8*9*64; l+=256){
      int ci=l/576; int rr=l%576; int t=rr>>6, oc=rr&63;
      sw[ci][t][oc] = g_w1t[((size_t)(icc+ci)*9+t)*128 + oct*64 + oc];
    }
    __syncthreads();
    for (int ci=0; ci<8; ci++){
      #pragma unroll
      for (int ky=0;ky<3;ky++){
        #pragma unroll
        for (int kx=0;kx<3;kx++){
          const float4 wv = *(const float4*)&sw[ci][ky*3+kx][ty*4];
          float w4[4] = {wv.x,wv.y,wv.z,wv.w};
          float iv[4];
          #pragma unroll
          for (int j=0;j<4;j++) iv[j]=sin[ci][py+ky][pxl+kx+j];
          #pragma unroll
          for (int i=0;i<4;i++)
            #pragma unroll
            for (int j=0;j<4;j++) acc[i][j] += w4[i]*iv[j];
        }
      }
    }
  }
  int yy = ty0+py, xb = tx0+pxl;
  #pragma unroll
  for (int i=0;i<4;i++){
    int oc = oct*64 + ty*4 + i;
    float bv = b1[oc];
    float4 o;
    o.x = fmaxf(acc[i][0]+bv, 0.f);
    o.y = fmaxf(acc[i][1]+bv, 0.f);
    o.z = fmaxf(acc[i][2]+bv, 0.f);
    o.w = fmaxf(acc[i][3]+bv, 0.f);
    *(float4*)&g_h[((size_t)(b*128+oc))*HWP + yy*WWD + xb] = o;
  }
}

// ---------------------------------------------------------------- conv2 128->2 3x3
__global__ void __launch_bounds__(256) conv2_kernel(const float* __restrict__ W2,
                                                    const float* __restrict__ b2,
                                                    float* __restrict__ out){
  __shared__ float sw2[128][9][2];
  __shared__ float sin2[8][10][34];
  const int b = blockIdx.z, y0 = blockIdx.y*8, x0 = blockIdx.x*32;
  const int tid = threadIdx.x;
  const int tx = tid&31, ty = tid>>5;
  for (int l=tid; l<2304; l+=256){
    int oc=l/1152; int r=l%1152; int ic=r/9, t=r%9;
    sw2[ic][t][oc] = W2[l];
  }
  float a0=0.f, a1=0.f;
  for (int icc=0; icc<128; icc+=8){
    __syncthreads();
    for (int l=tid; l<8*340; l+=256){
      int ci=l/340, r=(l/34)%10, cc=l%34;
      int yy=y0-1+r, xx=x0-1+cc;
      float v=0.f;
      if (yy>=0&&yy<HH&&xx>=0&&xx<WWD)
        v = g_h[((size_t)(b*128+icc+ci))*HWP + yy*WWD + xx];
      sin2[ci][r][cc]=v;
    }
    __syncthreads();
    #pragma unroll
    for (int ci=0;ci<8;ci++){
      #pragma unroll
      for (int ky=0;ky<3;ky++)
        #pragma unroll
        for (int kx=0;kx<3;kx++){
          float iv = sin2[ci][ty+ky][tx+kx];
          a0 += iv*sw2[icc+ci][ky*3+kx][0];
          a1 += iv*sw2[icc+ci][ky*3+kx][1];
        }
    }
  }
  int px = (y0+ty)*WWD + x0+tx;
  out[((size_t)(b*2+0))*HWP + px] = a0 + b2[0];
  out[((size_t)(b*2+1))*HWP + px] = a1 + b2[1];
}

// ---------------------------------------------------------------- launch
extern "C" void kernel_launch(void* const* d_in, const int* in_sizes, int n_in,
                              void* d_out, int out_size){
  const float* cur_embed  = (const float*)d_in[0];
  const float* cur_decode = (const float*)d_in[1];
  const float* init_embed = (const float*)d_in[2];
  const float* init_seg   = (const float*)d_in[3];
  const float* prev_embed = (const float*)d_in[4];
  const float* prev_seg   = (const float*)d_in[5];
  const float* W1 = (const float*)d_in[6];
  const float* b1 = (const float*)d_in[7];
  const float* W2 = (const float*)d_in[8];
  const float* b2 = (const float*)d_in[9];
  float* out = (float*)d_out;

  int pool_total = BB*CEMB*KP + BB*2*KP;
  pool_kernel<<<(pool_total+255)/256, 256>>>(init_embed, init_seg);
  prep_kernel<<<(128*264*9+255)/256, 256>>>(init_seg, prev_seg, W1);
  gmap_kernel<<<dim3(HWP/64, BB), 256>>>(cur_embed);
  corr_kernel<<<dim3(WWD/32, HH, BB), 256>>>(cur_embed, prev_embed, prev_seg);
  conv1_kernel<<<dim3(144, 2, BB), 256>>>(cur_decode, b1);
  conv2_kernel<<<dim3(WWD/32, HH/8, BB), 256>>>(W2, b2, out);
}

// round 4
// speedup vs baseline: 1.1731x; 1.1731x over previous
#include <cuda_runtime.h>

#define BB 8
#define CEMB 256
#define HH 96
#define WWD 96
#define HWP (HH*WWD)      // 9216
#define PH 24
#define PWd 24
#define KP (PH*PWd)       // 576

// scratch (static device globals — no runtime allocation)
__device__ float g_fi[BB*CEMB*KP];      // pooled init_embed (b,c,k)
__device__ float g_si[BB*2*KP];         // pooled init_seg   (b,s,k)
__device__ float g_extra[BB*8*HWP];     // ch: gmap0,gmap1,iseg0,iseg1,lmap0,lmap1,pseg0,pseg1
__device__ float g_h[BB*128*HWP];       // conv1 output
__device__ float g_w1t[264*9*128];      // W1 transposed to [ic][tap][oc], tf32-rounded

// ---------------------------------------------------------------- mma helpers
__device__ __forceinline__ unsigned tf32u(float x){
  unsigned y; asm("cvt.rna.tf32.f32 %0, %1;" : "=r"(y) : "f"(x)); return y;
}
__device__ __forceinline__ float tf32f(float x){ return __uint_as_float(tf32u(x)); }

__device__ __forceinline__ void mma_t(float c[4], const unsigned a[4], const unsigned b[2]){
  asm volatile("mma.sync.aligned.m16n8k8.row.col.f32.tf32.tf32.f32 "
      "{%0,%1,%2,%3}, {%4,%5,%6,%7}, {%8,%9}, {%0,%1,%2,%3};"
      : "+f"(c[0]),"+f"(c[1]),"+f"(c[2]),"+f"(c[3])
      : "r"(a[0]),"r"(a[1]),"r"(a[2]),"r"(a[3]), "r"(b[0]),"r"(b[1]));
}

// ---------------------------------------------------------------- pooling
__global__ void __launch_bounds__(256) pool_kernel(const float* __restrict__ init_embed,
                                                   const float* __restrict__ init_seg){
  int idx = blockIdx.x*256 + threadIdx.x;
  const int nfi = BB*CEMB*KP;
  if (idx < nfi){
    int k = idx % KP; int c = (idx/KP) % CEMB; int b = idx/(KP*CEMB);
    int py = k/PWd, px = k%PWd;
    const float* s = init_embed + (((size_t)(b*CEMB+c))*HH + py*4)*WWD + px*4;
    float acc = 0.f;
    #pragma unroll
    for (int i=0;i<4;i++)
      #pragma unroll
      for (int j=0;j<4;j++) acc += s[i*WWD+j];
    g_fi[idx] = acc*(1.f/16.f);
  } else if (idx < nfi + BB*2*KP){
    int r = idx - nfi;
    int k = r%KP; int c=(r/KP)%2; int b=r/(KP*2);
    int py=k/PWd, px=k%PWd;
    const float* s = init_seg + (((size_t)(b*2+c))*HH + py*4)*WWD + px*4;
    float acc=0.f;
    #pragma unroll
    for (int i=0;i<4;i++)
      #pragma unroll
      for (int j=0;j<4;j++) acc += s[i*WWD+j];
    g_si[r] = acc*(1.f/16.f);
  }
}

// ------------------------------------------- pack segs into extras + W1 transpose (tf32)
__global__ void __launch_bounds__(256) prep_kernel(const float* __restrict__ init_seg,
                                                   const float* __restrict__ prev_seg,
                                                   const float* __restrict__ W1){
  int idx = blockIdx.x*256 + threadIdx.x;
  if (idx < BB*2*HWP){
    int px = idx % HWP; int s=(idx/HWP)%2; int b=idx/(2*HWP);
    g_extra[((size_t)(b*8+2+s))*HWP + px] = init_seg[idx];
    g_extra[((size_t)(b*8+6+s))*HWP + px] = prev_seg[idx];
  }
  if (idx < 128*264*9){
    int t = idx%9; int ic=(idx/9)%264; int oc=idx/(264*9);
    g_w1t[((size_t)ic*9+t)*128 + oc] = tf32f(W1[idx]);
  }
}

// ---------------------------------------------------------------- gmap (tf32 MMA + max epilogue)
// block: 64 px x 576 k (looped 64 at a time), K=256 ch. 8 warps: 4 px-tiles x 2 k-halves.
__global__ void __launch_bounds__(256) gmap_kernel(const float* __restrict__ cur_embed){
  __shared__ float scur[16][65];
  __shared__ float sfi[16][65];
  __shared__ float ssi[2*KP];
  __shared__ float sred[2][2][64];
  const int b = blockIdx.y, px0 = blockIdx.x*64;
  const int tid = threadIdx.x, lane = tid&31, wid = tid>>5;
  const int mi = wid&3, kh = wid>>2;
  const int q = lane>>2, r4 = lane&3;
  for (int l=tid; l<2*KP; l+=256) ssi[l] = g_si[b*2*KP + l];
  const float* __restrict__ curb = cur_embed + (size_t)b*CEMB*HWP + px0;
  const float* __restrict__ fib  = g_fi + (size_t)b*CEMB*KP;
  float best[4];
  best[0]=best[1]=best[2]=best[3] = -1e30f;

  for (int kt=0; kt<KP; kt+=64){
    float acc[4][4];
    #pragma unroll
    for (int n=0;n<4;n++)
      #pragma unroll
      for (int i=0;i<4;i++) acc[n][i]=0.f;

    for (int ct=0; ct<CEMB; ct+=16){
      __syncthreads();
      #pragma unroll
      for (int i=0;i<4;i++){
        int e = tid + i*256; int ch = e>>6, p = e&63;
        scur[ch][p] = tf32f(curb[(size_t)(ct+ch)*HWP + p]);
        sfi[ch][p]  = tf32f(fib[(size_t)(ct+ch)*KP + kt + p]);
      }
      __syncthreads();
      #pragma unroll
      for (int c8=0;c8<16;c8+=8){
        unsigned a[4];
        a[0] = __float_as_uint(scur[c8+r4  ][mi*16+q  ]);
        a[1] = __float_as_uint(scur[c8+r4  ][mi*16+q+8]);
        a[2] = __float_as_uint(scur[c8+r4+4][mi*16+q  ]);
        a[3] = __float_as_uint(scur[c8+r4+4][mi*16+q+8]);
        #pragma unroll
        for (int nt=0;nt<4;nt++){
          unsigned bb[2];
          int kk = kh*32 + nt*8 + q;
          bb[0] = __float_as_uint(sfi[c8+r4  ][kk]);
          bb[1] = __float_as_uint(sfi[c8+r4+4][kk]);
          mma_t(acc[nt], a, bb);
        }
      }
    }
    // fold si weighting + running max over k (cols)
    #pragma unroll
    for (int nt=0;nt<4;nt++){
      int k0 = kt + kh*32 + nt*8 + r4*2;
      float s00 = ssi[k0], s01 = ssi[k0+1];
      float s10 = ssi[KP+k0], s11 = ssi[KP+k0+1];
      best[0] = fmaxf(best[0], fmaxf(acc[nt][0]*s00, acc[nt][1]*s01));
      best[1] = fmaxf(best[1], fmaxf(acc[nt][2]*s00, acc[nt][3]*s01));
      best[2] = fmaxf(best[2], fmaxf(acc[nt][0]*s10, acc[nt][1]*s11));
      best[3] = fmaxf(best[3], fmaxf(acc[nt][2]*s10, acc[nt][3]*s11));
    }
  }
  // reduce over the 4 lanes sharing a px row
  #pragma unroll
  for (int m=1;m<4;m<<=1)
    #pragma unroll
    for (int i=0;i<4;i++)
      best[i] = fmaxf(best[i], __shfl_xor_sync(0xffffffffu, best[i], m));
  if (r4==0){
    sred[kh][0][mi*16+q  ] = best[0];
    sred[kh][0][mi*16+q+8] = best[1];
    sred[kh][1][mi*16+q  ] = best[2];
    sred[kh][1][mi*16+q+8] = best[3];
  }
  __syncthreads();
  if (tid<128){
    int s = tid>>6, p = tid&63;
    g_extra[((size_t)(b*8+s))*HWP + px0 + p] = fmaxf(sred[0][s][p], sred[1][s][p]);
  }
}

// ---------------------------------------------------------------- local correlation (lmap)
__global__ void __launch_bounds__(256) corr_kernel(const float* __restrict__ cur_embed,
                                                   const float* __restrict__ prev_embed,
                                                   const float* __restrict__ prev_seg){
  __shared__ float scur[16][32];
  __shared__ float sprev[16][9][40];
  __shared__ float scorr[32][82];
  const int b = blockIdx.z, y = blockIdx.y, x0 = blockIdx.x*32;
  const int tid = threadIdx.x;
  for (int l=tid; l<32*82; l+=256) (&scorr[0][0])[l]=0.f;
  const int pg = tid&7, dxg = (tid>>3)%3, dy = tid/24;   // valid when tid<216

  for (int ct=0; ct<CEMB; ct+=16){
    __syncthreads();
    for (int l=tid; l<16*32; l+=256){
      int ci=l>>5, pp=l&31;
      scur[ci][pp] = cur_embed[(((size_t)(b*CEMB+ct+ci))*HH + y)*WWD + x0+pp];
    }
    for (int l=tid; l<16*9*40; l+=256){
      int ci=l/360, r=(l/40)%9, cc=l%40;
      int yy=y-4+r, xx=x0-4+cc;
      float v=0.f;
      if (yy>=0 && yy<HH && xx>=0 && xx<WWD)
        v = prev_embed[(((size_t)(b*CEMB+ct+ci))*HH+yy)*WWD+xx];
      sprev[ci][r][cc]=v;
    }
    __syncthreads();
    if (tid < 216){
      float a[3][4];
      #pragma unroll
      for (int d=0;d<3;d++)
        #pragma unroll
        for (int j=0;j<4;j++) a[d][j]=0.f;
      #pragma unroll
      for (int ci=0;ci<16;ci++){
        float cu[4], pv[6];
        #pragma unroll
        for (int j=0;j<4;j++) cu[j]=scur[ci][pg*4+j];
        #pragma unroll
        for (int t=0;t<6;t++) pv[t]=sprev[ci][dy][pg*4+dxg*3+t];
        #pragma unroll
        for (int d=0;d<3;d++)
          #pragma unroll
          for (int j=0;j<4;j++) a[d][j] += cu[j]*pv[d+j];
      }
      #pragma unroll
      for (int d=0;d<3;d++)
        #pragma unroll
        for (int j=0;j<4;j++)
          scorr[pg*4+j][dy*9+dxg*3+d] += a[d][j];
    }
  }
  __syncthreads();
  if (tid < 64){
    int s = tid>>5, px = tid&31;
    int xg = x0+px;
    const float* __restrict__ seg = prev_seg + ((size_t)(b*2+s))*HWP;
    float best = -1e30f;
    for (int d2=0; d2<9; d2++){
      int yy=y-4+d2;
      #pragma unroll
      for (int dx=0; dx<9; dx++){
        int xx=xg-4+dx;
        float sv = (yy>=0&&yy<HH&&xx>=0&&xx<WWD) ? seg[yy*WWD+xx] : 0.f;
        best = fmaxf(best, scorr[px][d2*9+dx]*(1.f/256.f)*sv);
      }
    }
    g_extra[((size_t)(b*8+4+s))*HWP + y*WWD + xg] = best;
  }
}

// ---------------------------------------------------------------- conv1 264->128 3x3 + relu (tf32 MMA)
// block: 128 oc x (16x8 px); 8 warps = 8 oc m-tiles; each warp 16oc x 128px (16 n-tiles).
__global__ void __launch_bounds__(256) conv1_kernel(const float* __restrict__ cur_decode,
                                                    const float* __restrict__ b1){
  __shared__ float sin[8][18][11];
  __shared__ float sw[8][9][130];
  const int b = blockIdx.y;
  const int ty0 = (blockIdx.x/12)*16, tx0 = (blockIdx.x%12)*8;
  const int tid = threadIdx.x, lane = tid&31, wid = tid>>5;
  const int q = lane>>2, r4 = lane&3;
  float acc[16][4];
  #pragma unroll
  for (int n=0;n<16;n++)
    #pragma unroll
    for (int i=0;i<4;i++) acc[n][i]=0.f;

  for (int icc=0; icc<264; icc+=8){
    __syncthreads();
    for (int l=tid; l<1440; l+=256){
      int ci=l/180, rr=(l/10)%18, cc=l%10;
      int ic=icc+ci, yy=ty0-1+rr, xx=tx0-1+cc;
      float v=0.f;
      if (yy>=0&&yy<HH&&xx>=0&&xx<WWD){
        v = (ic<256) ? cur_decode[(((size_t)(b*256+ic))*HH+yy)*WWD+xx]
                     : g_extra[((size_t)(b*8+ic-256))*HWP + yy*WWD+xx];
      }
      sin[ci][rr][cc] = tf32f(v);
    }
    for (int l=tid; l<9216; l+=256){
      int ci=l/1152, t=(l/128)%9, oc=l&127;
      sw[ci][t][oc] = g_w1t[((size_t)(icc+ci)*9+t)*128+oc];   // already tf32
    }
    __syncthreads();
    #pragma unroll
    for (int tap=0; tap<9; tap++){
      const int ky = tap/3, kx = tap%3;
      unsigned a[4];
      a[0] = __float_as_uint(sw[r4  ][tap][wid*16+q  ]);
      a[1] = __float_as_uint(sw[r4  ][tap][wid*16+q+8]);
      a[2] = __float_as_uint(sw[r4+4][tap][wid*16+q  ]);
      a[3] = __float_as_uint(sw[r4+4][tap][wid*16+q+8]);
      #pragma unroll
      for (int nt=0;nt<16;nt++){
        unsigned bb[2];
        bb[0] = __float_as_uint(sin[r4  ][nt+ky][q+kx]);
        bb[1] = __float_as_uint(sin[r4+4][nt+ky][q+kx]);
        mma_t(acc[nt], a, bb);
      }
    }
  }
  // epilogue: bias + relu, float2 stores
  const int oc0 = wid*16+q, oc1 = oc0+8;
  const float bv0 = b1[oc0], bv1 = b1[oc1];
  const int x0 = tx0 + r4*2;
  #pragma unroll
  for (int nt=0;nt<16;nt++){
    int y = ty0+nt;
    float2 o0, o1;
    o0.x = fmaxf(acc[nt][0]+bv0, 0.f); o0.y = fmaxf(acc[nt][1]+bv0, 0.f);
    o1.x = fmaxf(acc[nt][2]+bv1, 0.f); o1.y = fmaxf(acc[nt][3]+bv1, 0.f);
    *(float2*)&g_h[((size_t)(b*128+oc0))*HWP + y*WWD + x0] = o0;
    *(float2*)&g_h[((size_t)(b*128+oc1))*HWP + y*WWD + x0] = o1;
  }
}

// ---------------------------------------------------------------- conv2 128->2 3x3
__global__ void __launch_bounds__(256) conv2_kernel(const float* __restrict__ W2,
                                                    const float* __restrict__ b2,
                                                    float* __restrict__ out){
  __shared__ float sw2[128][9][2];
  __shared__ float sin2[8][10][34];
  const int b = blockIdx.z, y0 = blockIdx.y*8, x0 = blockIdx.x*32;
  const int tid = threadIdx.x;
  const int tx = tid&31, ty = tid>>5;
  for (int l=tid; l<2304; l+=256){
    int oc=l/1152; int r=l%1152; int ic=r/9, t=r%9;
    sw2[ic][t][oc] = W2[l];
  }
  float a0=0.f, a1=0.f;
  for (int icc=0; icc<128; icc+=8){
    __syncthreads();
    for (int l=tid; l<8*340; l+=256){
      int ci=l/340, r=(l/34)%10, cc=l%34;
      int yy=y0-1+r, xx=x0-1+cc;
      float v=0.f;
      if (yy>=0&&yy<HH&&xx>=0&&xx<WWD)
        v = g_h[((size_t)(b*128+icc+ci))*HWP + yy*WWD + xx];
      sin2[ci][r][cc]=v;
    }
    __syncthreads();
    #pragma unroll
    for (int ci=0;ci<8;ci++){
      #pragma unroll
      for (int ky=0;ky<3;ky++)
        #pragma unroll
        for (int kx=0;kx<3;kx++){
          float iv = sin2[ci][ty+ky][tx+kx];
          a0 += iv*sw2[icc+ci][ky*3+kx][0];
          a1 += iv*sw2[icc+ci][ky*3+kx][1];
        }
    }
  }
  int px = (y0+ty)*WWD + x0+tx;
  out[((size_t)(b*2+0))*HWP + px] = a0 + b2[0];
  out[((size_t)(b*2+1))*HWP + px] = a1 + b2[1];
}

// ---------------------------------------------------------------- launch
extern "C" void kernel_launch(void* const* d_in, const int* in_sizes, int n_in,
                              void* d_out, int out_size){
  const float* cur_embed  = (const float*)d_in[0];
  const float* cur_decode = (const float*)d_in[1];
  const float* init_embed = (const float*)d_in[2];
  const float* init_seg   = (const float*)d_in[3];
  const float* prev_embed = (const float*)d_in[4];
  const float* prev_seg   = (const float*)d_in[5];
  const float* W1 = (const float*)d_in[6];
  const float* b1 = (const float*)d_in[7];
  const float* W2 = (const float*)d_in[8];
  const float* b2 = (const float*)d_in[9];
  float* out = (float*)d_out;

  int pool_total = BB*CEMB*KP + BB*2*KP;
  pool_kernel<<<(pool_total+255)/256, 256>>>(init_embed, init_seg);
  prep_kernel<<<(128*264*9+255)/256, 256>>>(init_seg, prev_seg, W1);
  gmap_kernel<<<dim3(HWP/64, BB), 256>>>(cur_embed);
  corr_kernel<<<dim3(WWD/32, HH, BB), 256>>>(cur_embed, prev_embed, prev_seg);
  conv1_kernel<<<dim3(72, BB), 256>>>(cur_decode, b1);
  conv2_kernel<<<dim3(WWD/32, HH/8, BB), 256>>>(W2, b2, out);
}

// round 6
// speedup vs baseline: 1.2734x; 1.0855x over previous
#include <cuda_runtime.h>

#define BB 8
#define CEMB 256
#define HH 96
#define WWD 96
#define HWP (HH*WWD)      // 9216
#define PH 24
#define PWd 24
#define KP (PH*PWd)       // 576

__device__ float g_fi[BB*CEMB*KP];      // pooled init_embed (b,c,k)
__device__ float g_si[BB*2*KP];         // pooled init_seg   (b,s,k)
__device__ float g_extra[BB*8*HWP];     // ch: gmap0,gmap1,iseg0,iseg1,lmap0,lmap1,pseg0,pseg1
__device__ float g_h[BB*128*HWP];       // conv1 output
__device__ float g_w1t[264*9*128];      // W1 transposed to [ic][tap][oc], tf32-rounded

// ---------------------------------------------------------------- mma helpers
__device__ __forceinline__ unsigned tf32u(float x){
  unsigned y; asm("cvt.rna.tf32.f32 %0, %1;" : "=r"(y) : "f"(x)); return y;
}
__device__ __forceinline__ float tf32f(float x){ return __uint_as_float(tf32u(x)); }

__device__ __forceinline__ void mma_t(float c[4], const unsigned a[4], const unsigned b[2]){
  asm volatile("mma.sync.aligned.m16n8k8.row.col.f32.tf32.tf32.f32 "
      "{%0,%1,%2,%3}, {%4,%5,%6,%7}, {%8,%9}, {%0,%1,%2,%3};"
      : "+f"(c[0]),"+f"(c[1]),"+f"(c[2]),"+f"(c[3])
      : "r"(a[0]),"r"(a[1]),"r"(a[2]),"r"(a[3]), "r"(b[0]),"r"(b[1]));
}

// monotonic float->int key for shared atomicMax
__device__ __forceinline__ void amaxf(int* addr, float f){
  int k = __float_as_int(f);
  k = (k >= 0) ? k : (k ^ 0x7FFFFFFF);
  atomicMax(addr, k);
}
__device__ __forceinline__ float keyinv(int k){
  return __int_as_float(k >= 0 ? k : (k ^ 0x7FFFFFFF));
}

// ---------------------------------------------------------------- pooling (float4)
__global__ void __launch_bounds__(256) pool_kernel(const float* __restrict__ init_embed,
                                                   const float* __restrict__ init_seg){
  int idx = blockIdx.x*256 + threadIdx.x;
  const int nfi = BB*CEMB*KP;
  if (idx < nfi){
    int k = idx % KP; int c = (idx/KP) % CEMB; int b = idx/(KP*CEMB);
    int py = k/PWd, px = k%PWd;
    const float4* s = (const float4*)(init_embed + (((size_t)(b*CEMB+c))*HH + py*4)*WWD + px*4);
    float acc = 0.f;
    #pragma unroll
    for (int i=0;i<4;i++){ float4 v = s[i*(WWD/4)]; acc += v.x+v.y+v.z+v.w; }
    g_fi[idx] = acc*(1.f/16.f);
  } else if (idx < nfi + BB*2*KP){
    int r = idx - nfi;
    int k = r%KP; int c=(r/KP)%2; int b=r/(KP*2);
    int py=k/PWd, px=k%PWd;
    const float4* s = (const float4*)(init_seg + (((size_t)(b*2+c))*HH + py*4)*WWD + px*4);
    float acc=0.f;
    #pragma unroll
    for (int i=0;i<4;i++){ float4 v = s[i*(WWD/4)]; acc += v.x+v.y+v.z+v.w; }
    g_si[r] = acc*(1.f/16.f);
  }
}

// ------------------------------------------- pack segs into extras + W1 transpose (tf32)
__global__ void __launch_bounds__(256) prep_kernel(const float* __restrict__ init_seg,
                                                   const float* __restrict__ prev_seg,
                                                   const float* __restrict__ W1){
  int idx = blockIdx.x*256 + threadIdx.x;
  if (idx < BB*2*HWP){
    int px = idx % HWP; int s=(idx/HWP)%2; int b=idx/(2*HWP);
    g_extra[((size_t)(b*8+2+s))*HWP + px] = init_seg[idx];
    g_extra[((size_t)(b*8+6+s))*HWP + px] = prev_seg[idx];
  }
  if (idx < 128*264*9){
    int t = idx%9; int ic=(idx/9)%264; int oc=idx/(264*9);
    g_w1t[((size_t)ic*9+t)*128 + oc] = tf32f(W1[idx]);
  }
}

// ---------------------------------------------------------------- gmap (tf32 MMA + max epilogue)
// block: 64 px x 576 k (looped 64 at a time), 64-ch chunks. 8 warps: 4 px-tiles x 2 k-halves.
__global__ void __launch_bounds__(256) gmap_kernel(const float* __restrict__ cur_embed){
  __shared__ float scur[64][72];
  __shared__ float sfi[64][72];
  __shared__ float ssi[2*KP];
  __shared__ float sred[2][2][64];
  const int b = blockIdx.y, px0 = blockIdx.x*64;
  const int tid = threadIdx.x, lane = tid&31, wid = tid>>5;
  const int mi = wid&3, kh = wid>>2;
  const int q = lane>>2, r4 = lane&3;
  for (int l=tid; l<2*KP; l+=256) ssi[l] = g_si[b*2*KP + l];
  const float* __restrict__ curb = cur_embed + (size_t)b*CEMB*HWP + px0;
  const float* __restrict__ fib  = g_fi + (size_t)b*CEMB*KP;
  float best[4];
  best[0]=best[1]=best[2]=best[3] = -1e30f;

  for (int kt=0; kt<KP; kt+=64){
    float acc[4][4];
    #pragma unroll
    for (int n=0;n<4;n++)
      #pragma unroll
      for (int i=0;i<4;i++) acc[n][i]=0.f;

    for (int ct=0; ct<CEMB; ct+=64){
      __syncthreads();
      #pragma unroll
      for (int i=0;i<16;i++){
        int e = tid + i*256; int ch = e>>6, p = e&63;
        scur[ch][p] = tf32f(curb[(size_t)(ct+ch)*HWP + p]);
        sfi[ch][p]  = tf32f(fib[(size_t)(ct+ch)*KP + kt + p]);
      }
      __syncthreads();
      #pragma unroll
      for (int c8=0;c8<64;c8+=8){
        unsigned a[4];
        a[0] = __float_as_uint(scur[c8+r4  ][mi*16+q  ]);
        a[1] = __float_as_uint(scur[c8+r4  ][mi*16+q+8]);
        a[2] = __float_as_uint(scur[c8+r4+4][mi*16+q  ]);
        a[3] = __float_as_uint(scur[c8+r4+4][mi*16+q+8]);
        #pragma unroll
        for (int nt=0;nt<4;nt++){
          unsigned bb[2];
          int kk = kh*32 + nt*8 + q;
          bb[0] = __float_as_uint(sfi[c8+r4  ][kk]);
          bb[1] = __float_as_uint(sfi[c8+r4+4][kk]);
          mma_t(acc[nt], a, bb);
        }
      }
    }
    #pragma unroll
    for (int nt=0;nt<4;nt++){
      int k0 = kt + kh*32 + nt*8 + r4*2;
      float s00 = ssi[k0], s01 = ssi[k0+1];
      float s10 = ssi[KP+k0], s11 = ssi[KP+k0+1];
      best[0] = fmaxf(best[0], fmaxf(acc[nt][0]*s00, acc[nt][1]*s01));
      best[1] = fmaxf(best[1], fmaxf(acc[nt][2]*s00, acc[nt][3]*s01));
      best[2] = fmaxf(best[2], fmaxf(acc[nt][0]*s10, acc[nt][1]*s11));
      best[3] = fmaxf(best[3], fmaxf(acc[nt][2]*s10, acc[nt][3]*s11));
    }
  }
  #pragma unroll
  for (int m=1;m<4;m<<=1)
    #pragma unroll
    for (int i=0;i<4;i++)
      best[i] = fmaxf(best[i], __shfl_xor_sync(0xffffffffu, best[i], m));
  if (r4==0){
    sred[kh][0][mi*16+q  ] = best[0];
    sred[kh][0][mi*16+q+8] = best[1];
    sred[kh][1][mi*16+q  ] = best[2];
    sred[kh][1][mi*16+q+8] = best[3];
  }
  __syncthreads();
  if (tid<128){
    int s = tid>>6, p = tid&63;
    g_extra[((size_t)(b*8+s))*HWP + px0 + p] = fmaxf(sred[0][s][p], sred[1][s][p]);
  }
}

// ---------------------------------------------------------------- local correlation (tf32 MMA)
// GEMM per block: A[360 rows=(dy,xx)] x B[32 px], K=256. Band-select + seg-weight epilogue.
__global__ void __launch_bounds__(256) corr_kernel(const float* __restrict__ cur_embed,
                                                   const float* __restrict__ prev_embed,
                                                   const float* __restrict__ prev_seg){
  __shared__ float sprevF[16*408];   // [ch][r], r = dy*40+xx, stride 408 (%32==24)
  __shared__ float scur[16][40];     // [ch][px], stride 40 (%32==8)
  __shared__ float sseg[2][400];     // seg value at flat r
  __shared__ int   sbest[2][32];
  const int b = blockIdx.z, y = blockIdx.y, x0 = blockIdx.x*32;
  const int tid = threadIdx.x, lane = tid&31, wid = tid>>5;
  const int q = lane>>2, r4 = lane&3;

  // seg tile + best init
  for (int l=tid; l<800; l+=256){
    int s = l/400, r = l%400;
    int rr = r/40, cc = r%40;
    int yy = y-4+rr, xx = x0-4+cc;
    float v = 0.f;
    if (rr<9 && yy>=0 && yy<HH && xx>=0 && xx<WWD)
      v = prev_seg[((size_t)(b*2+s))*HWP + yy*WWD + xx];
    sseg[s][r] = v;
  }
  if (tid < 64) sbest[tid>>5][tid&31] = 0x80000000;

  float acc[3][4][4];
  #pragma unroll
  for (int t=0;t<3;t++)
    #pragma unroll
    for (int n=0;n<4;n++)
      #pragma unroll
      for (int i=0;i<4;i++) acc[t][n][i]=0.f;

  const int r0base = wid*16 + q;   // row for m=q in tile mt=wid+8t

  for (int ct=0; ct<CEMB; ct+=16){
    __syncthreads();
    // fill prev tile: 16ch x 10 rows x 40 cols (row 9 = zeros for M-padding)
    for (int rowid=wid; rowid<160; rowid+=8){
      int ci = rowid/10, rr = rowid - ci*10;
      int yy = y-4+rr;
      const float* src = prev_embed + (((size_t)(b*CEMB+ct+ci))*HH + yy)*WWD + (x0-4);
      bool rowok = (rr<9) && (yy>=0) && (yy<HH);
      for (int cc=lane; cc<40; cc+=32){
        int xx = x0-4+cc;
        float v = (rowok && xx>=0 && xx<WWD) ? src[cc] : 0.f;
        sprevF[ci*408 + rr*40 + cc] = tf32f(v);
      }
    }
    // fill cur tile
    for (int rowid=wid; rowid<16; rowid+=8)
      scur[rowid][lane] = tf32f(cur_embed[(((size_t)(b*CEMB+ct+rowid))*HH + y)*WWD + x0 + lane]);
    __syncthreads();
    #pragma unroll
    for (int ks=0; ks<2; ks++){
      const int k0 = ks*8;
      unsigned bf[4][2];
      #pragma unroll
      for (int nt=0;nt<4;nt++){
        bf[nt][0] = __float_as_uint(scur[k0+r4  ][nt*8+q]);
        bf[nt][1] = __float_as_uint(scur[k0+r4+4][nt*8+q]);
      }
      const float* pA = sprevF + (k0+r4)*408;
      #pragma unroll
      for (int t=0;t<3;t++){
        int mt = wid + 8*t;
        if (mt > 22) break;
        int r0 = r0base + 128*t, r1 = r0 + 8;
        unsigned a[4];
        a[0] = __float_as_uint(pA[r0]);
        a[1] = __float_as_uint(pA[r1]);
        a[2] = __float_as_uint(pA[4*408 + r0]);
        a[3] = __float_as_uint(pA[4*408 + r1]);
        #pragma unroll
        for (int nt=0;nt<4;nt++) mma_t(acc[t][nt], a, bf[nt]);
      }
    }
  }
  __syncthreads();
  // epilogue: band select + seg weight + shared atomic max
  const float inv256 = 1.f/256.f;
  #pragma unroll
  for (int t=0;t<3;t++){
    int mt = wid + 8*t;
    if (mt > 22) break;
    int r0 = r0base + 128*t, r1 = r0 + 8;
    int xx0 = r0 % 40, xx1 = r1 % 40;
    bool v0 = (r0 < 360), v1 = (r1 < 360);
    float sA0 = sseg[0][r0], sA1 = sseg[1][r0];
    float sB0 = sseg[0][r1], sB1 = sseg[1][r1];
    #pragma unroll
    for (int nt=0;nt<4;nt++){
      int pxl = nt*8 + r4*2;
      int d;
      d = xx0 - pxl;
      if (v0 && d>=0 && d<=8){ float v = acc[t][nt][0]*inv256;
        amaxf(&sbest[0][pxl], v*sA0); amaxf(&sbest[1][pxl], v*sA1); }
      d = xx0 - pxl - 1;
      if (v0 && d>=0 && d<=8){ float v = acc[t][nt][1]*inv256;
        amaxf(&sbest[0][pxl+1], v*sA0); amaxf(&sbest[1][pxl+1], v*sA1); }
      d = xx1 - pxl;
      if (v1 && d>=0 && d<=8){ float v = acc[t][nt][2]*inv256;
        amaxf(&sbest[0][pxl], v*sB0); amaxf(&sbest[1][pxl], v*sB1); }
      d = xx1 - pxl - 1;
      if (v1 && d>=0 && d<=8){ float v = acc[t][nt][3]*inv256;
        amaxf(&sbest[0][pxl+1], v*sB0); amaxf(&sbest[1][pxl+1], v*sB1); }
    }
  }
  __syncthreads();
  if (tid < 64){
    int s = tid>>5, px = tid&31;
    g_extra[((size_t)(b*8+4+s))*HWP + y*WWD + x0 + px] = keyinv(sbest[s][px]);
  }
}

// ---------------------------------------------------------------- conv1 264->128 3x3 + relu (tf32 MMA)
// block: 128 oc x (16x8 px); 8 warps = 8 oc m-tiles. kx-outer rolling B window.
__global__ void __launch_bounds__(256) conv1_kernel(const float* __restrict__ cur_decode,
                                                    const float* __restrict__ b1){
  __shared__ float sin[8][18][12];    // ci stride 216 (%32==24): conflict-free
  __shared__ float sw[8][9][136];     // ci stride 1224 (%32==8): conflict-free
  const int b = blockIdx.y;
  const int ty0 = (blockIdx.x/12)*16, tx0 = (blockIdx.x%12)*8;
  const int tid = threadIdx.x, lane = tid&31, wid = tid>>5;
  const int q = lane>>2, r4 = lane&3;
  float acc[16][4];
  #pragma unroll
  for (int n=0;n<16;n++)
    #pragma unroll
    for (int i=0;i<4;i++) acc[n][i]=0.f;

  for (int icc=0; icc<264; icc+=8){
    __syncthreads();
    for (int l=tid; l<1440; l+=256){
      int ci=l/180, rr=(l/10)%18, cc=l%10;
      int ic=icc+ci, yy=ty0-1+rr, xx=tx0-1+cc;
      float v=0.f;
      if (yy>=0&&yy<HH&&xx>=0&&xx<WWD){
        v = (ic<256) ? cur_decode[(((size_t)(b*256+ic))*HH+yy)*WWD+xx]
                     : g_extra[((size_t)(b*8+ic-256))*HWP + yy*WWD+xx];
      }
      sin[ci][rr][cc] = tf32f(v);
    }
    for (int l=tid; l<9216; l+=256){
      int ci=l/1152, t=(l/128)%9, oc=l&127;
      sw[ci][t][oc] = g_w1t[((size_t)(icc+ci)*9+t)*128+oc];
    }
    __syncthreads();
    #pragma unroll
    for (int kx=0; kx<3; kx++){
      unsigned aK[3][4];
      #pragma unroll
      for (int ky=0; ky<3; ky++){
        int tap = ky*3+kx;
        aK[ky][0] = __float_as_uint(sw[r4  ][tap][wid*16+q  ]);
        aK[ky][1] = __float_as_uint(sw[r4  ][tap][wid*16+q+8]);
        aK[ky][2] = __float_as_uint(sw[r4+4][tap][wid*16+q  ]);
        aK[ky][3] = __float_as_uint(sw[r4+4][tap][wid*16+q+8]);
      }
      unsigned br[3][2];
      br[0][0] = __float_as_uint(sin[r4  ][0][q+kx]);
      br[0][1] = __float_as_uint(sin[r4+4][0][q+kx]);
      br[1][0] = __float_as_uint(sin[r4  ][1][q+kx]);
      br[1][1] = __float_as_uint(sin[r4+4][1][q+kx]);
      #pragma unroll
      for (int nt=0; nt<16; nt++){
        br[(nt+2)%3][0] = __float_as_uint(sin[r4  ][nt+2][q+kx]);
        br[(nt+2)%3][1] = __float_as_uint(sin[r4+4][nt+2][q+kx]);
        mma_t(acc[nt], aK[0], br[ nt   %3]);
        mma_t(acc[nt], aK[1], br[(nt+1)%3]);
        mma_t(acc[nt], aK[2], br[(nt+2)%3]);
      }
    }
  }
  const int oc0 = wid*16+q, oc1 = oc0+8;
  const float bv0 = b1[oc0], bv1 = b1[oc1];
  const int x0 = tx0 + r4*2;
  #pragma unroll
  for (int nt=0;nt<16;nt++){
    int y = ty0+nt;
    float2 o0, o1;
    o0.x = fmaxf(acc[nt][0]+bv0, 0.f); o0.y = fmaxf(acc[nt][1]+bv0, 0.f);
    o1.x = fmaxf(acc[nt][2]+bv1, 0.f); o1.y = fmaxf(acc[nt][3]+bv1, 0.f);
    *(float2*)&g_h[((size_t)(b*128+oc0))*HWP + y*WWD + x0] = o0;
    *(float2*)&g_h[((size_t)(b*128+oc1))*HWP + y*WWD + x0] = o1;
  }
}

// ---------------------------------------------------------------- conv2 128->2 3x3
__global__ void __launch_bounds__(256) conv2_kernel(const float* __restrict__ W2,
                                                    const float* __restrict__ b2,
                                                    float* __restrict__ out){
  __shared__ float sw2[128][9][2];
  __shared__ float sin2[8][10][34];
  const int b = blockIdx.z, y0 = blockIdx.y*8, x0 = blockIdx.x*32;
  const int tid = threadIdx.x;
  const int tx = tid&31, ty = tid>>5;
  for (int l=tid; l<2304; l+=256){
    int oc=l/1152; int r=l%1152; int ic=r/9, t=r%9;
    sw2[ic][t][oc] = W2[l];
  }
  float a0=0.f, a1=0.f;
  for (int icc=0; icc<128; icc+=8){
    __syncthreads();
    for (int l=tid; l<8*340; l+=256){
      int ci=l/340, r=(l/34)%10, cc=l%34;
      int yy=y0-1+r, xx=x0-1+cc;
      float v=0.f;
      if (yy>=0&&yy<HH&&xx>=0&&xx<WWD)
        v = g_h[((size_t)(b*128+icc+ci))*HWP + yy*WWD + xx];
      sin2[ci][r][cc]=v;
    }
    __syncthreads();
    #pragma unroll
    for (int ci=0;ci<8;ci++){
      #pragma unroll
      for (int ky=0;ky<3;ky++)
        #pragma unroll
        for (int kx=0;kx<3;kx++){
          float iv = sin2[ci][ty+ky][tx+kx];
          a0 += iv*sw2[icc+ci][ky*3+kx][0];
          a1 += iv*sw2[icc+ci][ky*3+kx][1];
        }
    }
  }
  int px = (y0+ty)*WWD + x0+tx;
  out[((size_t)(b*2+0))*HWP + px] = a0 + b2[0];
  out[((size_t)(b*2+1))*HWP + px] = a1 + b2[1];
}

// ---------------------------------------------------------------- launch
extern "C" void kernel_launch(void* const* d_in, const int* in_sizes, int n_in,
                              void* d_out, int out_size){
  const float* cur_embed  = (const float*)d_in[0];
  const float* cur_decode = (const float*)d_in[1];
  const float* init_embed = (const float*)d_in[2];
  const float* init_seg   = (const float*)d_in[3];
  const float* prev_embed = (const float*)d_in[4];
  const float* prev_seg   = (const float*)d_in[5];
  const float* W1 = (const float*)d_in[6];
  const float* b1 = (const float*)d_in[7];
  const float* W2 = (const float*)d_in[8];
  const float* b2 = (const float*)d_in[9];
  float* out = (float*)d_out;

  int pool_total = BB*CEMB*KP + BB*2*KP;
  pool_kernel<<<(pool_total+255)/256, 256>>>(init_embed, init_seg);
  prep_kernel<<<(128*264*9+255)/256, 256>>>(init_seg, prev_seg, W1);
  gmap_kernel<<<dim3(HWP/64, BB), 256>>>(cur_embed);
  corr_kernel<<<dim3(WWD/32, HH, BB), 256>>>(cur_embed, prev_embed, prev_seg);
  conv1_kernel<<<dim3(72, BB), 256>>>(cur_decode, b1);
  conv2_kernel<<<dim3(WWD/32, HH/8, BB), 256>>>(W2, b2, out);
}

// round 12
// speedup vs baseline: 1.9115x; 1.5011x over previous
#include <cuda_runtime.h>

#define BB 8
#define CEMB 256
#define HH 96
#define WWD 96
#define HWP (HH*WWD)      // 9216
#define PH 24
#define PWd 24
#define KP (PH*PWd)       // 576
#define NYC 4             // y-rows per corr block

__device__ float g_fi[BB*CEMB*KP];      // pooled init_embed (b,c,k)
__device__ float g_si[BB*2*KP];         // pooled init_seg   (b,s,k)
__device__ float g_extra[BB*8*HWP];     // ch: gmap0,gmap1,iseg0,iseg1,lmap0,lmap1,pseg0,pseg1
__device__ float g_h[BB*128*HWP];       // conv1 output
__device__ float g_w1t[264*9*128];      // W1 transposed to [ic][tap][oc], tf32-rounded

// ---------------------------------------------------------------- mma helpers
__device__ __forceinline__ unsigned tf32u(float x){
  unsigned y; asm("cvt.rna.tf32.f32 %0, %1;" : "=r"(y) : "f"(x)); return y;
}
__device__ __forceinline__ float tf32f(float x){ return __uint_as_float(tf32u(x)); }

__device__ __forceinline__ void mma_t(float c[4], const unsigned a[4], const unsigned b[2]){
  asm volatile("mma.sync.aligned.m16n8k8.row.col.f32.tf32.tf32.f32 "
      "{%0,%1,%2,%3}, {%4,%5,%6,%7}, {%8,%9}, {%0,%1,%2,%3};"
      : "+f"(c[0]),"+f"(c[1]),"+f"(c[2]),"+f"(c[3])
      : "r"(a[0]),"r"(a[1]),"r"(a[2]),"r"(a[3]), "r"(b[0]),"r"(b[1]));
}

// monotonic float->int key for shared atomicMax
__device__ __forceinline__ void amaxf(int* addr, float f){
  int k = __float_as_int(f);
  k = (k >= 0) ? k : (k ^ 0x7FFFFFFF);
  atomicMax(addr, k);
}
__device__ __forceinline__ float keyinv(int k){
  return __int_as_float(k >= 0 ? k : (k ^ 0x7FFFFFFF));
}

// ---------------------------------------------------------------- pooling (float4)
__global__ void __launch_bounds__(256) pool_kernel(const float* __restrict__ init_embed,
                                                   const float* __restrict__ init_seg){
  int idx = blockIdx.x*256 + threadIdx.x;
  const int nfi = BB*CEMB*KP;
  if (idx < nfi){
    int k = idx % KP; int c = (idx/KP) % CEMB; int b = idx/(KP*CEMB);
    int py = k/PWd, px = k%PWd;
    const float4* s = (const float4*)(init_embed + (((size_t)(b*CEMB+c))*HH + py*4)*WWD + px*4);
    float acc = 0.f;
    #pragma unroll
    for (int i=0;i<4;i++){ float4 v = s[i*(WWD/4)]; acc += v.x+v.y+v.z+v.w; }
    g_fi[idx] = acc*(1.f/16.f);
  } else if (idx < nfi + BB*2*KP){
    int r = idx - nfi;
    int k = r%KP; int c=(r/KP)%2; int b=r/(KP*2);
    int py=k/PWd, px=k%PWd;
    const float4* s = (const float4*)(init_seg + (((size_t)(b*2+c))*HH + py*4)*WWD + px*4);
    float acc=0.f;
    #pragma unroll
    for (int i=0;i<4;i++){ float4 v = s[i*(WWD/4)]; acc += v.x+v.y+v.z+v.w; }
    g_si[r] = acc*(1.f/16.f);
  }
}

// ------------------------------------------- pack segs into extras + W1 transpose (tf32)
__global__ void __launch_bounds__(256) prep_kernel(const float* __restrict__ init_seg,
                                                   const float* __restrict__ prev_seg,
                                                   const float* __restrict__ W1){
  int idx = blockIdx.x*256 + threadIdx.x;
  if (idx < BB*2*HWP){
    int px = idx % HWP; int s=(idx/HWP)%2; int b=idx/(2*HWP);
    g_extra[((size_t)(b*8+2+s))*HWP + px] = init_seg[idx];
    g_extra[((size_t)(b*8+6+s))*HWP + px] = prev_seg[idx];
  }
  if (idx < 128*264*9){
    int t = idx%9; int ic=(idx/9)%264; int oc=idx/(264*9);
    g_w1t[((size_t)ic*9+t)*128 + oc] = tf32f(W1[idx]);
  }
}

// ---------------------------------------------------------------- gmap (tf32 MMA + max epilogue)
__global__ void __launch_bounds__(256) gmap_kernel(const float* __restrict__ cur_embed){
  __shared__ float scur[64][72];
  __shared__ float sfi[64][72];
  __shared__ float ssi[2*KP];
  __shared__ float sred[2][2][64];
  const int b = blockIdx.y, px0 = blockIdx.x*64;
  const int tid = threadIdx.x, lane = tid&31, wid = tid>>5;
  const int mi = wid&3, kh = wid>>2;
  const int q = lane>>2, r4 = lane&3;
  for (int l=tid; l<2*KP; l+=256) ssi[l] = g_si[b*2*KP + l];
  const float* __restrict__ curb = cur_embed + (size_t)b*CEMB*HWP + px0;
  const float* __restrict__ fib  = g_fi + (size_t)b*CEMB*KP;
  float best[4];
  best[0]=best[1]=best[2]=best[3] = -1e30f;

  for (int kt=0; kt<KP; kt+=64){
    float acc[4][4];
    #pragma unroll
    for (int n=0;n<4;n++)
      #pragma unroll
      for (int i=0;i<4;i++) acc[n][i]=0.f;

    for (int ct=0; ct<CEMB; ct+=64){
      __syncthreads();
      #pragma unroll
      for (int i=0;i<16;i++){
        int e = tid + i*256; int ch = e>>6, p = e&63;
        scur[ch][p] = tf32f(curb[(size_t)(ct+ch)*HWP + p]);
        sfi[ch][p]  = tf32f(fib[(size_t)(ct+ch)*KP + kt + p]);
      }
      __syncthreads();
      #pragma unroll
      for (int c8=0;c8<64;c8+=8){
        unsigned a[4];
        a[0] = __float_as_uint(scur[c8+r4  ][mi*16+q  ]);
        a[1] = __float_as_uint(scur[c8+r4  ][mi*16+q+8]);
        a[2] = __float_as_uint(scur[c8+r4+4][mi*16+q  ]);
        a[3] = __float_as_uint(scur[c8+r4+4][mi*16+q+8]);
        #pragma unroll
        for (int nt=0;nt<4;nt++){
          unsigned bb[2];
          int kk = kh*32 + nt*8 + q;
          bb[0] = __float_as_uint(sfi[c8+r4  ][kk]);
          bb[1] = __float_as_uint(sfi[c8+r4+4][kk]);
          mma_t(acc[nt], a, bb);
        }
      }
    }
    #pragma unroll
    for (int nt=0;nt<4;nt++){
      int k0 = kt + kh*32 + nt*8 + r4*2;
      float s00 = ssi[k0], s01 = ssi[k0+1];
      float s10 = ssi[KP+k0], s11 = ssi[KP+k0+1];
      best[0] = fmaxf(best[0], fmaxf(acc[nt][0]*s00, acc[nt][1]*s01));
      best[1] = fmaxf(best[1], fmaxf(acc[nt][2]*s00, acc[nt][3]*s01));
      best[2] = fmaxf(best[2], fmaxf(acc[nt][0]*s10, acc[nt][1]*s11));
      best[3] = fmaxf(best[3], fmaxf(acc[nt][2]*s10, acc[nt][3]*s11));
    }
  }
  #pragma unroll
  for (int m=1;m<4;m<<=1)
    #pragma unroll
    for (int i=0;i<4;i++)
      best[i] = fmaxf(best[i], __shfl_xor_sync(0xffffffffu, best[i], m));
  if (r4==0){
    sred[kh][0][mi*16+q  ] = best[0];
    sred[kh][0][mi*16+q+8] = best[1];
    sred[kh][1][mi*16+q  ] = best[2];
    sred[kh][1][mi*16+q+8] = best[3];
  }
  __syncthreads();
  if (tid<128){
    int s = tid>>6, p = tid&63;
    g_extra[((size_t)(b*8+s))*HWP + px0 + p] = fmaxf(sred[0][s][p], sred[1][s][p]);
  }
}

// ---------------------------------------------------------------- local correlation (scalar fp32, y-blocked)
// block: 4 y-rows x 32 px. thread = (4px group, dy, ylocal); 36 acc (9dx x 4px).
__global__ void __launch_bounds__(288) corr_kernel(const float* __restrict__ cur_embed,
                                                   const float* __restrict__ prev_embed,
                                                   const float* __restrict__ prev_seg){
  __shared__ float scur[16][NYC][32];
  __shared__ float sprev[16][NYC+8][40];
  __shared__ float sseg[2][NYC+8][40];
  __shared__ int   sbest[2][NYC][32];
  const int b = blockIdx.z, y0 = blockIdx.y*NYC, x0 = blockIdx.x*32;
  const int tid = threadIdx.x;
  const int pg = tid&7, dy = (tid>>3)%9, yl = tid/72;

  // seg halo (zero-padded) + best init
  for (int l=tid; l<2*(NYC+8)*40; l+=288){
    int s = l/((NYC+8)*40), rem = l%((NYC+8)*40), r = rem/40, c = rem%40;
    int yy = y0-4+r, xx = x0-4+c;
    float v = 0.f;
    if (yy>=0 && yy<HH && xx>=0 && xx<WWD)
      v = prev_seg[((size_t)(b*2+s))*HWP + yy*WWD + xx];
    sseg[s][r][c] = v;
  }
  if (tid < 2*NYC*32)
    ((int*)sbest)[tid] = 0x80000000;

  float acc[9][4];
  #pragma unroll
  for (int d=0;d<9;d++)
    #pragma unroll
    for (int j=0;j<4;j++) acc[d][j]=0.f;

  for (int ct=0; ct<CEMB; ct+=16){
    __syncthreads();
    for (int l=tid; l<16*NYC*32; l+=288){
      int ci = l>>7, rem = l&127, r = rem>>5, c = rem&31;
      scur[ci][r][c] = cur_embed[(((size_t)(b*CEMB+ct+ci))*HH + y0+r)*WWD + x0+c];
    }
    for (int l=tid; l<16*(NYC+8)*40; l+=288){
      int ci = l/((NYC+8)*40), rem = l%((NYC+8)*40), r = rem/40, c = rem%40;
      int yy = y0-4+r, xx = x0-4+c;
      float v = 0.f;
      if (yy>=0 && yy<HH && xx>=0 && xx<WWD)
        v = prev_embed[(((size_t)(b*CEMB+ct+ci))*HH+yy)*WWD+xx];
      sprev[ci][r][c] = v;
    }
    __syncthreads();
    #pragma unroll
    for (int ci=0;ci<16;ci++){
      const float4 c4 = *(const float4*)&scur[ci][yl][pg*4];
      const float4 p0 = *(const float4*)&sprev[ci][yl+dy][pg*4];
      const float4 p1 = *(const float4*)&sprev[ci][yl+dy][pg*4+4];
      const float4 p2 = *(const float4*)&sprev[ci][yl+dy][pg*4+8];
      float cu[4] = {c4.x,c4.y,c4.z,c4.w};
      float pv[12] = {p0.x,p0.y,p0.z,p0.w, p1.x,p1.y,p1.z,p1.w, p2.x,p2.y,p2.z,p2.w};
      #pragma unroll
      for (int d=0;d<9;d++)
        #pragma unroll
        for (int j=0;j<4;j++)
          acc[d][j] += cu[j]*pv[d+j];
    }
  }
  // epilogue: reduce over d in registers, ONE atomic per (s,j)
  const float inv = 1.f/256.f;
  #pragma unroll
  for (int j=0;j<4;j++){
    int px = pg*4+j;
    float b0 = -1e30f, b1 = -1e30f;
    #pragma unroll
    for (int d=0;d<9;d++){
      float v = acc[d][j]*inv;
      b0 = fmaxf(b0, v*sseg[0][yl+dy][px+d]);
      b1 = fmaxf(b1, v*sseg[1][yl+dy][px+d]);
    }
    amaxf(&sbest[0][yl][px], b0);
    amaxf(&sbest[1][yl][px], b1);
  }
  __syncthreads();
  if (tid < 2*NYC*32){
    int s = tid/(NYC*32), rem = tid%(NYC*32), yw = rem>>5, px = rem&31;
    g_extra[((size_t)(b*8+4+s))*HWP + (y0+yw)*WWD + x0+px] = keyinv(sbest[s][yw][px]);
  }
}

// ---------------------------------------------------------------- conv1 264->128 3x3 + relu (tf32 MMA)
__global__ void __launch_bounds__(256) conv1_kernel(const float* __restrict__ cur_decode,
                                                    const float* __restrict__ b1){
  __shared__ float sin[8][18][12];
  __shared__ float sw[8][9][136];
  const int b = blockIdx.y;
  const int ty0 = (blockIdx.x/12)*16, tx0 = (blockIdx.x%12)*8;
  const int tid = threadIdx.x, lane = tid&31, wid = tid>>5;
  const int q = lane>>2, r4 = lane&3;
  float acc[16][4];
  #pragma unroll
  for (int n=0;n<16;n++)
    #pragma unroll
    for (int i=0;i<4;i++) acc[n][i]=0.f;

  for (int icc=0; icc<264; icc+=8){
    __syncthreads();
    for (int l=tid; l<1440; l+=256){
      int ci=l/180, rr=(l/10)%18, cc=l%10;
      int ic=icc+ci, yy=ty0-1+rr, xx=tx0-1+cc;
      float v=0.f;
      if (yy>=0&&yy<HH&&xx>=0&&xx<WWD){
        v = (ic<256) ? cur_decode[(((size_t)(b*256+ic))*HH+yy)*WWD+xx]
                     : g_extra[((size_t)(b*8+ic-256))*HWP + yy*WWD+xx];
      }
      sin[ci][rr][cc] = tf32f(v);
    }
    for (int l=tid; l<9216; l+=256){
      int ci=l/1152, t=(l/128)%9, oc=l&127;
      sw[ci][t][oc] = g_w1t[((size_t)(icc+ci)*9+t)*128+oc];
    }
    __syncthreads();
    #pragma unroll
    for (int kx=0; kx<3; kx++){
      unsigned aK[3][4];
      #pragma unroll
      for (int ky=0; ky<3; ky++){
        int tap = ky*3+kx;
        aK[ky][0] = __float_as_uint(sw[r4  ][tap][wid*16+q  ]);
        aK[ky][1] = __float_as_uint(sw[r4  ][tap][wid*16+q+8]);
        aK[ky][2] = __float_as_uint(sw[r4+4][tap][wid*16+q  ]);
        aK[ky][3] = __float_as_uint(sw[r4+4][tap][wid*16+q+8]);
      }
      unsigned br[3][2];
      br[0][0] = __float_as_uint(sin[r4  ][0][q+kx]);
      br[0][1] = __float_as_uint(sin[r4+4][0][q+kx]);
      br[1][0] = __float_as_uint(sin[r4  ][1][q+kx]);
      br[1][1] = __float_as_uint(sin[r4+4][1][q+kx]);
      #pragma unroll
      for (int nt=0; nt<16; nt++){
        br[(nt+2)%3][0] = __float_as_uint(sin[r4  ][nt+2][q+kx]);
        br[(nt+2)%3][1] = __float_as_uint(sin[r4+4][nt+2][q+kx]);
        mma_t(acc[nt], aK[0], br[ nt   %3]);
        mma_t(acc[nt], aK[1], br[(nt+1)%3]);
        mma_t(acc[nt], aK[2], br[(nt+2)%3]);
      }
    }
  }
  const int oc0 = wid*16+q, oc1 = oc0+8;
  const float bv0 = b1[oc0], bv1 = b1[oc1];
  const int x0 = tx0 + r4*2;
  #pragma unroll
  for (int nt=0;nt<16;nt++){
    int y = ty0+nt;
    float2 o0, o1;
    o0.x = fmaxf(acc[nt][0]+bv0, 0.f); o0.y = fmaxf(acc[nt][1]+bv0, 0.f);
    o1.x = fmaxf(acc[nt][2]+bv1, 0.f); o1.y = fmaxf(acc[nt][3]+bv1, 0.f);
    *(float2*)&g_h[((size_t)(b*128+oc0))*HWP + y*WWD + x0] = o0;
    *(float2*)&g_h[((size_t)(b*128+oc1))*HWP + y*WWD + x0] = o1;
  }
}

// ---------------------------------------------------------------- conv2 128->2 3x3
__global__ void __launch_bounds__(256) conv2_kernel(const float* __restrict__ W2,
                                                    const float* __restrict__ b2,
                                                    float* __restrict__ out){
  __shared__ float sw2[128][9][2];
  __shared__ float sin2[8][10][34];
  const int b = blockIdx.z, y0 = blockIdx.y*8, x0 = blockIdx.x*32;
  const int tid = threadIdx.x;
  const int tx = tid&31, ty = tid>>5;
  for (int l=tid; l<2304; l+=256){
    int oc=l/1152; int r=l%1152; int ic=r/9, t=r%9;
    sw2[ic][t][oc] = W2[l];
  }
  float a0=0.f, a1=0.f;
  for (int icc=0; icc<128; icc+=8){
    __syncthreads();
    for (int l=tid; l<8*340; l+=256){
      int ci=l/340, r=(l/34)%10, cc=l%34;
      int yy=y0-1+r, xx=x0-1+cc;
      float v=0.f;
      if (yy>=0&&yy<HH&&xx>=0&&xx<WWD)
        v = g_h[((size_t)(b*128+icc+ci))*HWP + yy*WWD + xx];
      sin2[ci][r][cc]=v;
    }
    __syncthreads();
    #pragma unroll
    for (int ci=0;ci<8;ci++){
      #pragma unroll
      for (int ky=0;ky<3;ky++)
        #pragma unroll
        for (int kx=0;kx<3;kx++){
          float iv = sin2[ci][ty+ky][tx+kx];
          a0 += iv*sw2[icc+ci][ky*3+kx][0];
          a1 += iv*sw2[icc+ci][ky*3+kx][1];
        }
    }
  }
  int px = (y0+ty)*WWD + x0+tx;
  out[((size_t)(b*2+0))*HWP + px] = a0 + b2[0];
  out[((size_t)(b*2+1))*HWP + px] = a1 + b2[1];
}

// ---------------------------------------------------------------- launch
extern "C" void kernel_launch(void* const* d_in, const int* in_sizes, int n_in,
                              void* d_out, int out_size){
  const float* cur_embed  = (const float*)d_in[0];
  const float* cur_decode = (const float*)d_in[1];
  const float* init_embed = (const float*)d_in[2];
  const float* init_seg   = (const float*)d_in[3];
  const float* prev_embed = (const float*)d_in[4];
  const float* prev_seg   = (const float*)d_in[5];
  const float* W1 = (const float*)d_in[6];
  const float* b1 = (const float*)d_in[7];
  const float* W2 = (const float*)d_in[8];
  const float* b2 = (const float*)d_in[9];
  float* out = (float*)d_out;

  int pool_total = BB*CEMB*KP + BB*2*KP;
  pool_kernel<<<(pool_total+255)/256, 256>>>(init_embed, init_seg);
  prep_kernel<<<(128*264*9+255)/256, 256>>>(init_seg, prev_seg, W1);
  gmap_kernel<<<dim3(HWP/64, BB), 256>>>(cur_embed);
  corr_kernel<<<dim3(WWD/32, HH/NYC, BB), 288>>>(cur_embed, prev_embed, prev_seg);
  conv1_kernel<<<dim3(72, BB), 256>>>(cur_decode, b1);
  conv2_kernel<<<dim3(WWD/32, HH/8, BB), 256>>>(W2, b2, out);
}